// round 1
// baseline (speedup 1.0000x reference)
#include <cuda_runtime.h>
#include <cstdint>
#include <cstdio>

#define D_MODEL 1024
#define NHEADS  16
#define HDIM    64
#define WINDOW  256
#define BATCH   2
#define SEQ     2048
#define MTOT    (BATCH * SEQ)          /* 4096 rows */
#define QKV_LD  (3 * D_MODEL)          /* 3072 */

// Scratch: no cudaMalloc allowed -> __device__ globals.
__device__ float g_qkv[(size_t)MTOT * QKV_LD];     // [B*L, 3*D]  (q|k|v interleaved per row)
__device__ float g_att[(size_t)MTOT * D_MODEL];    // [B*L, D] attention output

// ---------------------------------------------------------------------------
// C[M,N] = A[M,K] * B[N,K]^T + bias[N]   (both operands K-contiguous, "NT")
// 128x128 block tile, BK=16, 256 threads, 8x8 per-thread microtile.
// ---------------------------------------------------------------------------
__global__ __launch_bounds__(256)
void gemm_nt_bias(const float* __restrict__ A, const float* __restrict__ B,
                  const float* __restrict__ bias, float* __restrict__ C,
                  int M, int N, int K)
{
    __shared__ float As[16][128];
    __shared__ float Bs[16][128];

    const int tid = threadIdx.x;
    const int bm  = blockIdx.y * 128;
    const int bn  = blockIdx.x * 128;
    const int tx  = tid & 15;          // n direction (16)
    const int ty  = tid >> 4;          // m direction (16)
    const int lr  = tid >> 2;          // load row 0..63
    const int lc  = (tid & 3) << 2;    // load col {0,4,8,12}

    const float* Ap = A + (size_t)(bm + lr) * K + lc;
    const float* Bp = B + (size_t)(bn + lr) * K + lc;

    float acc[8][8];
#pragma unroll
    for (int i = 0; i < 8; ++i)
#pragma unroll
        for (int j = 0; j < 8; ++j) acc[i][j] = 0.f;

    for (int k0 = 0; k0 < K; k0 += 16) {
        float4 a0 = *(const float4*)(Ap + k0);
        float4 a1 = *(const float4*)(Ap + (size_t)64 * K + k0);
        float4 b0 = *(const float4*)(Bp + k0);
        float4 b1 = *(const float4*)(Bp + (size_t)64 * K + k0);

        As[lc+0][lr]    = a0.x; As[lc+1][lr]    = a0.y; As[lc+2][lr]    = a0.z; As[lc+3][lr]    = a0.w;
        As[lc+0][lr+64] = a1.x; As[lc+1][lr+64] = a1.y; As[lc+2][lr+64] = a1.z; As[lc+3][lr+64] = a1.w;
        Bs[lc+0][lr]    = b0.x; Bs[lc+1][lr]    = b0.y; Bs[lc+2][lr]    = b0.z; Bs[lc+3][lr]    = b0.w;
        Bs[lc+0][lr+64] = b1.x; Bs[lc+1][lr+64] = b1.y; Bs[lc+2][lr+64] = b1.z; Bs[lc+3][lr+64] = b1.w;
        __syncthreads();

#pragma unroll
        for (int kk = 0; kk < 16; ++kk) {
            float ar[8], br[8];
            *(float4*)&ar[0] = *(const float4*)&As[kk][ty * 8];
            *(float4*)&ar[4] = *(const float4*)&As[kk][ty * 8 + 4];
            *(float4*)&br[0] = *(const float4*)&Bs[kk][tx * 8];
            *(float4*)&br[4] = *(const float4*)&Bs[kk][tx * 8 + 4];
#pragma unroll
            for (int i = 0; i < 8; ++i)
#pragma unroll
                for (int j = 0; j < 8; ++j)
                    acc[i][j] = fmaf(ar[i], br[j], acc[i][j]);
        }
        __syncthreads();
    }

#pragma unroll
    for (int i = 0; i < 8; ++i) {
        float* cp = C + (size_t)(bm + ty * 8 + i) * N + bn + tx * 8;
#pragma unroll
        for (int j = 0; j < 8; j += 4) {
            float4 o;
            o.x = acc[i][j+0] + bias[bn + tx*8 + j + 0];
            o.y = acc[i][j+1] + bias[bn + tx*8 + j + 1];
            o.z = acc[i][j+2] + bias[bn + tx*8 + j + 2];
            o.w = acc[i][j+3] + bias[bn + tx*8 + j + 3];
            *(float4*)(cp + j) = o;
        }
    }
}

// ---------------------------------------------------------------------------
// Sliding-window attention. One block = one (b,h) x 64-query tile; one thread
// = one query row (online softmax fully thread-local, no reductions).
// Window [i-255, i] for 64 aligned queries == exactly 5 key tiles of 64.
// K/V smem reads are uniform across the warp -> pure broadcast, conflict-free.
// ---------------------------------------------------------------------------
__global__ __launch_bounds__(64)
void swa_kernel(const float* __restrict__ qkv, float* __restrict__ out)
{
    __shared__ float Ks[64][64];
    __shared__ float Vs[64][64];

    const int t  = threadIdx.x;
    const int bh = blockIdx.y;
    const int b  = bh >> 4;
    const int h  = bh & 15;
    const int q0 = blockIdx.x * 64;
    const int i  = q0 + t;

    const size_t rowbase = (size_t)(b * SEQ) * QKV_LD + (size_t)h * HDIM;

    float qr[64];
    {
        const float* qp = qkv + rowbase + (size_t)i * QKV_LD;
#pragma unroll
        for (int e = 0; e < 64; e += 4) {
            float4 v = *(const float4*)(qp + e);
            qr[e] = v.x; qr[e+1] = v.y; qr[e+2] = v.z; qr[e+3] = v.w;
        }
    }

    float acc[64];
#pragma unroll
    for (int e = 0; e < 64; ++e) acc[e] = 0.f;
    float m = -1e30f, ssum = 0.f;

    const int kt0 = max(0, (q0 >> 6) - 4);
    const int kt1 = q0 >> 6;

    for (int kt = kt0; kt <= kt1; ++kt) {
        const int j0 = kt << 6;
        __syncthreads();
        // cooperative load of K and V tiles (coalesced float4)
        for (int idx = t; idx < 64 * 16; idx += 64) {
            const int row = idx >> 4, col = idx & 15;
            const size_t rb = rowbase + (size_t)(j0 + row) * QKV_LD;
            ((float4*)&Ks[row][0])[col] = ((const float4*)(qkv + rb + D_MODEL))[col];
            ((float4*)&Vs[row][0])[col] = ((const float4*)(qkv + rb + 2 * D_MODEL))[col];
        }
        __syncthreads();

        for (int jc = 0; jc < 64; jc += 8) {
            float s[8];
#pragma unroll
            for (int jj = 0; jj < 8; ++jj) {
                const float* kr = &Ks[jc + jj][0];
                float d0 = 0.f, d1 = 0.f, d2 = 0.f, d3 = 0.f;
#pragma unroll
                for (int e = 0; e < 64; e += 4) {
                    d0 = fmaf(qr[e+0], kr[e+0], d0);
                    d1 = fmaf(qr[e+1], kr[e+1], d1);
                    d2 = fmaf(qr[e+2], kr[e+2], d2);
                    d3 = fmaf(qr[e+3], kr[e+3], d3);
                }
                const int jg = j0 + jc + jj;
                const bool valid = (jg <= i) && (jg + WINDOW > i);
                s[jj] = valid ? (d0 + d1 + d2 + d3) * 0.125f : -1e30f;
            }
            float mc = m;
#pragma unroll
            for (int jj = 0; jj < 8; ++jj) mc = fmaxf(mc, s[jj]);
            const float scale = __expf(m - mc);
            m = mc;
            ssum *= scale;
#pragma unroll
            for (int e = 0; e < 64; ++e) acc[e] *= scale;
#pragma unroll
            for (int jj = 0; jj < 8; ++jj) {
                const float p = (s[jj] > -1e29f) ? __expf(s[jj] - mc) : 0.f;
                ssum += p;
                const float* vr = &Vs[jc + jj][0];
#pragma unroll
                for (int e = 0; e < 64; ++e)
                    acc[e] = fmaf(p, vr[e], acc[e]);
            }
        }
    }

    const float inv = 1.f / ssum;
    float* op = out + (size_t)(b * SEQ + i) * D_MODEL + (size_t)h * HDIM;
#pragma unroll
    for (int e = 0; e < 64; e += 4) {
        float4 o = make_float4(acc[e] * inv, acc[e+1] * inv, acc[e+2] * inv, acc[e+3] * inv);
        *(float4*)(op + e) = o;
    }
}

// ---------------------------------------------------------------------------
extern "C" void kernel_launch(void* const* d_in, const int* in_sizes, int n_in,
                              void* d_out, int out_size)
{
    const float* x      = (const float*)d_in[0];
    const float* w_qkv  = (const float*)d_in[1];
    const float* b_qkv  = (const float*)d_in[2];
    const float* w_proj = (const float*)d_in[3];
    const float* b_proj = (const float*)d_in[4];
    float* out = (float*)d_out;

    float *qkv_p = nullptr, *att_p = nullptr;
    cudaGetSymbolAddress((void**)&qkv_p, g_qkv);   // query only, capture-safe
    cudaGetSymbolAddress((void**)&att_p, g_att);

    // 1) QKV projection: [4096,1024] x [3072,1024]^T
    gemm_nt_bias<<<dim3(QKV_LD / 128, MTOT / 128), 256>>>(
        x, w_qkv, b_qkv, qkv_p, MTOT, QKV_LD, D_MODEL);

    // 2) sliding-window attention -> [B*L, D]
    swa_kernel<<<dim3(SEQ / 64, BATCH * NHEADS), 64>>>(qkv_p, att_p);

    // 3) output projection: [4096,1024] x [1024,1024]^T
    gemm_nt_bias<<<dim3(D_MODEL / 128, MTOT / 128), 256>>>(
        att_p, w_proj, b_proj, out, MTOT, D_MODEL, D_MODEL);
}

// round 3
// speedup vs baseline: 1.6932x; 1.6932x over previous
#include <cuda_runtime.h>
#include <cuda_bf16.h>
#include <cstdint>

#define D_MODEL 1024
#define NHEADS  16
#define HDIM    64
#define WINDOW  256
#define BATCH   2
#define SEQ     2048
#define MTOT    (BATCH * SEQ)          /* 4096 */
#define QKV_LD  (3 * D_MODEL)          /* 3072 */

// ---- scratch (no cudaMalloc allowed) --------------------------------------
__device__ float        g_qkv[(size_t)MTOT * QKV_LD];
__device__ __nv_bfloat16 g_xhi[(size_t)MTOT * D_MODEL];
__device__ __nv_bfloat16 g_xlo[(size_t)MTOT * D_MODEL];
__device__ __nv_bfloat16 g_wqh[(size_t)QKV_LD * D_MODEL];
__device__ __nv_bfloat16 g_wql[(size_t)QKV_LD * D_MODEL];
__device__ __nv_bfloat16 g_wph[(size_t)D_MODEL * D_MODEL];
__device__ __nv_bfloat16 g_wpl[(size_t)D_MODEL * D_MODEL];
__device__ __nv_bfloat16 g_ahi[(size_t)MTOT * D_MODEL];
__device__ __nv_bfloat16 g_alo[(size_t)MTOT * D_MODEL];

// ---- PTX helpers (compute_103-baseline only: mma.sync + cp.async) ----------
__device__ __forceinline__ uint32_t smem_u32(const void* p) {
    uint32_t a;
    asm("{ .reg .u64 t; cvta.to.shared.u64 t, %1; cvt.u32.u64 %0, t; }" : "=r"(a) : "l"(p));
    return a;
}
__device__ __forceinline__ void cp16(uint32_t dst, const void* src) {
    asm volatile("cp.async.cg.shared.global [%0], [%1], 16;" :: "r"(dst), "l"(src));
}
#define CP_COMMIT()  asm volatile("cp.async.commit_group;" ::: "memory")
#define CP_WAIT(n)   asm volatile("cp.async.wait_group %0;" :: "n"(n) : "memory")

__device__ __forceinline__ void mma_bf16(float* d, uint32_t a0, uint32_t a1,
                                         uint32_t a2, uint32_t a3,
                                         uint32_t b0, uint32_t b1) {
    asm volatile(
        "mma.sync.aligned.m16n8k16.row.col.f32.bf16.bf16.f32 "
        "{%0,%1,%2,%3}, {%4,%5,%6,%7}, {%8,%9}, {%0,%1,%2,%3};"
        : "+f"(d[0]), "+f"(d[1]), "+f"(d[2]), "+f"(d[3])
        : "r"(a0), "r"(a1), "r"(a2), "r"(a3), "r"(b0), "r"(b1));
}

// ---- hi/lo bf16 split -------------------------------------------------------
__global__ __launch_bounds__(256)
void split_bf16(const float4* __restrict__ in, __nv_bfloat16* __restrict__ hi,
                __nv_bfloat16* __restrict__ lo, int n4)
{
    int i = blockIdx.x * 256 + threadIdx.x;
    if (i >= n4) return;
    float4 v = in[i];
    __nv_bfloat16 h0 = __float2bfloat16(v.x), h1 = __float2bfloat16(v.y);
    __nv_bfloat16 h2 = __float2bfloat16(v.z), h3 = __float2bfloat16(v.w);
    __nv_bfloat162* hp = (__nv_bfloat162*)(hi + i * 4);
    __nv_bfloat162* lp = (__nv_bfloat162*)(lo + i * 4);
    hp[0] = __nv_bfloat162(h0, h1);
    hp[1] = __nv_bfloat162(h2, h3);
    lp[0] = __nv_bfloat162(__float2bfloat16(v.x - __bfloat162float(h0)),
                           __float2bfloat16(v.y - __bfloat162float(h1)));
    lp[1] = __nv_bfloat162(__float2bfloat16(v.z - __bfloat162float(h2)),
                           __float2bfloat16(v.w - __bfloat162float(h3)));
}

// ---- bf16x3 mma.sync GEMM: C[M,N] = (Ahi+Alo)[M,K]*(Bhi+Blo)[N,K]^T + bias --
// 128x128 CTA tile, BK=32, 256 threads (8 warps = 2m x 4n), warp tile 64x32.
#define BM 128
#define BN 128
#define BK 32
#define SROW 40                        /* 32 + 8 pad, bf16 elems; 80B stride */
#define TILE_E (128 * SROW)            /* elems per operand tile */
#define STAGE_E (4 * TILE_E)           /* Ahi,Alo,Bhi,Blo */
#define SMEM_SZ (2 * STAGE_E * 2)      /* bytes, 2 stages */

__global__ __launch_bounds__(256, 1)
void gemm_bf16x3(const __nv_bfloat16* __restrict__ Ahi, const __nv_bfloat16* __restrict__ Alo,
                 const __nv_bfloat16* __restrict__ Bhi, const __nv_bfloat16* __restrict__ Blo,
                 const float* __restrict__ bias, float* __restrict__ C,
                 int M, int N, int K)
{
    extern __shared__ __nv_bfloat16 smem[];
    const int tid  = threadIdx.x;
    const int lane = tid & 31;
    const int wid  = tid >> 5;
    const int wm   = wid >> 2;           // 0..1
    const int wn   = wid & 3;            // 0..3
    const int tr   = lane >> 2;          // 0..7
    const int tc2  = (lane & 3) * 2;     // 0,2,4,6
    const int bm   = blockIdx.y * BM;
    const int bn   = blockIdx.x * BN;

    const uint32_t sbase = smem_u32(smem);

    float acc[4][4][4];
#pragma unroll
    for (int i = 0; i < 4; ++i)
#pragma unroll
        for (int j = 0; j < 4; ++j)
#pragma unroll
            for (int r = 0; r < 4; ++r) acc[i][j][r] = 0.f;

    // gmem->smem stage loader (cp.async). granule: 16B = 8 bf16.
    const __nv_bfloat16* srcs[4] = { Ahi, Alo, Bhi, Blo };
    const int rowoff[4] = { bm, bm, bn, bn };

    auto load_stage = [&](int s, int k0) {
        const uint32_t st = sbase + (uint32_t)(s * STAGE_E * 2);
#pragma unroll
        for (int t = 0; t < 4; ++t) {
#pragma unroll
            for (int g2 = 0; g2 < 2; ++g2) {
                const int g = tid + g2 * 256;        // 0..511
                const int row = g >> 2, part = g & 3;
                const uint32_t dst = st + (uint32_t)(t * TILE_E + row * SROW + part * 8) * 2;
                const __nv_bfloat16* src = srcs[t] + (size_t)(rowoff[t] + row) * K + k0 + part * 8;
                cp16(dst, src);
            }
        }
    };

    const int KCH = K / BK;
    load_stage(0, 0);
    CP_COMMIT();

    for (int c = 0; c < KCH; ++c) {
        if (c + 1 < KCH) {
            load_stage((c + 1) & 1, (c + 1) * BK);
            CP_COMMIT();
            CP_WAIT(1);
        } else {
            CP_WAIT(0);
        }
        __syncthreads();

        const __nv_bfloat16* stg = smem + (c & 1) * STAGE_E;
        const __nv_bfloat16* Ah = stg;
        const __nv_bfloat16* Al = stg + TILE_E;
        const __nv_bfloat16* Bh = stg + 2 * TILE_E;
        const __nv_bfloat16* Bl = stg + 3 * TILE_E;

#pragma unroll
        for (int k0 = 0; k0 < BK; k0 += 16) {
            uint32_t ah[4][4], al[4][4], bh[4][2], bl[4][2];
#pragma unroll
            for (int mi = 0; mi < 4; ++mi) {
                const int base = (wm * 64 + mi * 16 + tr) * SROW + k0 + tc2;
                ah[mi][0] = *(const uint32_t*)(Ah + base);
                ah[mi][1] = *(const uint32_t*)(Ah + base + 8 * SROW);
                ah[mi][2] = *(const uint32_t*)(Ah + base + 8);
                ah[mi][3] = *(const uint32_t*)(Ah + base + 8 * SROW + 8);
                al[mi][0] = *(const uint32_t*)(Al + base);
                al[mi][1] = *(const uint32_t*)(Al + base + 8 * SROW);
                al[mi][2] = *(const uint32_t*)(Al + base + 8);
                al[mi][3] = *(const uint32_t*)(Al + base + 8 * SROW + 8);
            }
#pragma unroll
            for (int ni = 0; ni < 4; ++ni) {
                const int base = (wn * 32 + ni * 8 + tr) * SROW + k0 + tc2;
                bh[ni][0] = *(const uint32_t*)(Bh + base);
                bh[ni][1] = *(const uint32_t*)(Bh + base + 8);
                bl[ni][0] = *(const uint32_t*)(Bl + base);
                bl[ni][1] = *(const uint32_t*)(Bl + base + 8);
            }
#pragma unroll
            for (int mi = 0; mi < 4; ++mi)
#pragma unroll
                for (int ni = 0; ni < 4; ++ni) {
                    mma_bf16(acc[mi][ni], ah[mi][0], ah[mi][1], ah[mi][2], ah[mi][3],
                             bh[ni][0], bh[ni][1]);
                    mma_bf16(acc[mi][ni], al[mi][0], al[mi][1], al[mi][2], al[mi][3],
                             bh[ni][0], bh[ni][1]);
                    mma_bf16(acc[mi][ni], ah[mi][0], ah[mi][1], ah[mi][2], ah[mi][3],
                             bl[ni][0], bl[ni][1]);
                }
        }
        __syncthreads();
    }

    // epilogue: d0,d1 = (r, c..c+1); d2,d3 = (r+8, c..c+1)
#pragma unroll
    for (int mi = 0; mi < 4; ++mi) {
        const int r = bm + wm * 64 + mi * 16 + tr;
#pragma unroll
        for (int ni = 0; ni < 4; ++ni) {
            const int cidx = bn + wn * 32 + ni * 8 + tc2;
            const float b0 = bias[cidx], b1 = bias[cidx + 1];
            float2 v0 = make_float2(acc[mi][ni][0] + b0, acc[mi][ni][1] + b1);
            float2 v1 = make_float2(acc[mi][ni][2] + b0, acc[mi][ni][3] + b1);
            *(float2*)(C + (size_t)r * N + cidx)       = v0;
            *(float2*)(C + (size_t)(r + 8) * N + cidx) = v1;
        }
    }
}

// ---- sliding-window attention (epilogue writes bf16 hi/lo) ------------------
__global__ __launch_bounds__(64)
void swa_kernel(const float* __restrict__ qkv,
                __nv_bfloat16* __restrict__ ohi, __nv_bfloat16* __restrict__ olo)
{
    __shared__ float Ks[64][64];
    __shared__ float Vs[64][64];

    const int t  = threadIdx.x;
    const int bh = blockIdx.y;
    const int b  = bh >> 4;
    const int h  = bh & 15;
    const int q0 = blockIdx.x * 64;
    const int i  = q0 + t;

    const size_t rowbase = (size_t)(b * SEQ) * QKV_LD + (size_t)h * HDIM;

    float qr[64];
    {
        const float* qp = qkv + rowbase + (size_t)i * QKV_LD;
#pragma unroll
        for (int e = 0; e < 64; e += 4) {
            float4 v = *(const float4*)(qp + e);
            qr[e] = v.x; qr[e+1] = v.y; qr[e+2] = v.z; qr[e+3] = v.w;
        }
    }

    float acc[64];
#pragma unroll
    for (int e = 0; e < 64; ++e) acc[e] = 0.f;
    float m = -1e30f, ssum = 0.f;

    const int kt0 = max(0, (q0 >> 6) - 4);
    const int kt1 = q0 >> 6;

    for (int kt = kt0; kt <= kt1; ++kt) {
        const int j0 = kt << 6;
        __syncthreads();
        for (int idx = t; idx < 64 * 16; idx += 64) {
            const int row = idx >> 4, col = idx & 15;
            const size_t rb = rowbase + (size_t)(j0 + row) * QKV_LD;
            ((float4*)&Ks[row][0])[col] = ((const float4*)(qkv + rb + D_MODEL))[col];
            ((float4*)&Vs[row][0])[col] = ((const float4*)(qkv + rb + 2 * D_MODEL))[col];
        }
        __syncthreads();

        for (int jc = 0; jc < 64; jc += 8) {
            float s[8];
#pragma unroll
            for (int jj = 0; jj < 8; ++jj) {
                const float* kr = &Ks[jc + jj][0];
                float d0 = 0.f, d1 = 0.f, d2 = 0.f, d3 = 0.f;
#pragma unroll
                for (int e = 0; e < 64; e += 4) {
                    d0 = fmaf(qr[e+0], kr[e+0], d0);
                    d1 = fmaf(qr[e+1], kr[e+1], d1);
                    d2 = fmaf(qr[e+2], kr[e+2], d2);
                    d3 = fmaf(qr[e+3], kr[e+3], d3);
                }
                const int jg = j0 + jc + jj;
                const bool valid = (jg <= i) && (jg + WINDOW > i);
                s[jj] = valid ? (d0 + d1 + d2 + d3) * 0.125f : -1e30f;
            }
            float mc = m;
#pragma unroll
            for (int jj = 0; jj < 8; ++jj) mc = fmaxf(mc, s[jj]);
            const float scale = __expf(m - mc);
            m = mc;
            ssum *= scale;
#pragma unroll
            for (int e = 0; e < 64; ++e) acc[e] *= scale;
#pragma unroll
            for (int jj = 0; jj < 8; ++jj) {
                const float p = (s[jj] > -1e29f) ? __expf(s[jj] - mc) : 0.f;
                ssum += p;
                const float* vr = &Vs[jc + jj][0];
#pragma unroll
                for (int e = 0; e < 64; ++e)
                    acc[e] = fmaf(p, vr[e], acc[e]);
            }
        }
    }

    const float inv = 1.f / ssum;
    const size_t ob = (size_t)(b * SEQ + i) * D_MODEL + (size_t)h * HDIM;
#pragma unroll
    for (int e = 0; e < 64; e += 2) {
        float o0 = acc[e] * inv, o1 = acc[e+1] * inv;
        __nv_bfloat16 h0 = __float2bfloat16(o0), h1 = __float2bfloat16(o1);
        *(__nv_bfloat162*)(ohi + ob + e) = __nv_bfloat162(h0, h1);
        *(__nv_bfloat162*)(olo + ob + e) = __nv_bfloat162(
            __float2bfloat16(o0 - __bfloat162float(h0)),
            __float2bfloat16(o1 - __bfloat162float(h1)));
    }
}

// ---------------------------------------------------------------------------
extern "C" void kernel_launch(void* const* d_in, const int* in_sizes, int n_in,
                              void* d_out, int out_size)
{
    const float* x      = (const float*)d_in[0];
    const float* w_qkv  = (const float*)d_in[1];
    const float* b_qkv  = (const float*)d_in[2];
    const float* w_proj = (const float*)d_in[3];
    const float* b_proj = (const float*)d_in[4];
    float* out = (float*)d_out;

    float* qkv_p;
    __nv_bfloat16 *xhi, *xlo, *wqh, *wql, *wph, *wpl, *ahi, *alo;
    cudaGetSymbolAddress((void**)&qkv_p, g_qkv);
    cudaGetSymbolAddress((void**)&xhi, g_xhi);
    cudaGetSymbolAddress((void**)&xlo, g_xlo);
    cudaGetSymbolAddress((void**)&wqh, g_wqh);
    cudaGetSymbolAddress((void**)&wql, g_wql);
    cudaGetSymbolAddress((void**)&wph, g_wph);
    cudaGetSymbolAddress((void**)&wpl, g_wpl);
    cudaGetSymbolAddress((void**)&ahi, g_ahi);
    cudaGetSymbolAddress((void**)&alo, g_alo);

    cudaFuncSetAttribute(gemm_bf16x3,
                         cudaFuncAttributeMaxDynamicSharedMemorySize, SMEM_SZ);

    {
        int n4x = MTOT * D_MODEL / 4;
        int n4q = QKV_LD * D_MODEL / 4;
        int n4p = D_MODEL * D_MODEL / 4;
        split_bf16<<<n4x / 256, 256>>>((const float4*)x, xhi, xlo, n4x);
        split_bf16<<<n4q / 256, 256>>>((const float4*)w_qkv, wqh, wql, n4q);
        split_bf16<<<n4p / 256, 256>>>((const float4*)w_proj, wph, wpl, n4p);
    }

    // 1) QKV projection (bf16x3 tensor-core)
    gemm_bf16x3<<<dim3(QKV_LD / BN, MTOT / BM), 256, SMEM_SZ>>>(
        xhi, xlo, wqh, wql, b_qkv, qkv_p, MTOT, QKV_LD, D_MODEL);

    // 2) sliding-window attention -> bf16 hi/lo
    swa_kernel<<<dim3(SEQ / 64, BATCH * NHEADS), 64>>>(qkv_p, ahi, alo);

    // 3) output projection (bf16x3 tensor-core)
    gemm_bf16x3<<<dim3(D_MODEL / BN, MTOT / BM), 256, SMEM_SZ>>>(
        ahi, alo, wph, wpl, b_proj, out, MTOT, D_MODEL, D_MODEL);
}

// round 5
// speedup vs baseline: 2.3400x; 1.3820x over previous
#include <cuda_runtime.h>
#include <cuda_bf16.h>
#include <cstdint>

#define D_MODEL 1024
#define NHEADS  16
#define HDIM    64
#define WINDOW  256
#define BATCH   2
#define SEQ     2048
#define MTOT    (BATCH * SEQ)          /* 4096 */
#define QKV_LD  (3 * D_MODEL)          /* 3072 */

// ---- scratch (no cudaMalloc allowed) --------------------------------------
__device__ float        g_qkv[(size_t)MTOT * QKV_LD];
__device__ __nv_bfloat16 g_xhi[(size_t)MTOT * D_MODEL];
__device__ __nv_bfloat16 g_xlo[(size_t)MTOT * D_MODEL];
__device__ __nv_bfloat16 g_wqh[(size_t)QKV_LD * D_MODEL];
__device__ __nv_bfloat16 g_wql[(size_t)QKV_LD * D_MODEL];
__device__ __nv_bfloat16 g_wph[(size_t)D_MODEL * D_MODEL];
__device__ __nv_bfloat16 g_wpl[(size_t)D_MODEL * D_MODEL];
__device__ __nv_bfloat16 g_ahi[(size_t)MTOT * D_MODEL];
__device__ __nv_bfloat16 g_alo[(size_t)MTOT * D_MODEL];

// ---- PTX helpers (compute_103 baseline: mma.sync + cp.async) ---------------
__device__ __forceinline__ uint32_t smem_u32(const void* p) {
    uint32_t a;
    asm("{ .reg .u64 t; cvta.to.shared.u64 t, %1; cvt.u32.u64 %0, t; }" : "=r"(a) : "l"(p));
    return a;
}
__device__ __forceinline__ void cp16(uint32_t dst, const void* src) {
    asm volatile("cp.async.cg.shared.global [%0], [%1], 16;" :: "r"(dst), "l"(src));
}
#define CP_COMMIT()  asm volatile("cp.async.commit_group;" ::: "memory")
#define CP_WAIT(n)   asm volatile("cp.async.wait_group %0;" :: "n"(n) : "memory")

__device__ __forceinline__ void mma_bf16(float* d, uint32_t a0, uint32_t a1,
                                         uint32_t a2, uint32_t a3,
                                         uint32_t b0, uint32_t b1) {
    asm volatile(
        "mma.sync.aligned.m16n8k16.row.col.f32.bf16.bf16.f32 "
        "{%0,%1,%2,%3}, {%4,%5,%6,%7}, {%8,%9}, {%0,%1,%2,%3};"
        : "+f"(d[0]), "+f"(d[1]), "+f"(d[2]), "+f"(d[3])
        : "r"(a0), "r"(a1), "r"(a2), "r"(a3), "r"(b0), "r"(b1));
}
__device__ __forceinline__ uint32_t pack_bf16(float a, float b) {
    __nv_bfloat162 t(__float2bfloat16(a), __float2bfloat16(b));
    return *(uint32_t*)&t;
}

// ---- hi/lo bf16 split -------------------------------------------------------
__global__ __launch_bounds__(256)
void split_bf16(const float4* __restrict__ in, __nv_bfloat16* __restrict__ hi,
                __nv_bfloat16* __restrict__ lo, int n4)
{
    int i = blockIdx.x * 256 + threadIdx.x;
    if (i >= n4) return;
    float4 v = in[i];
    __nv_bfloat16 h0 = __float2bfloat16(v.x), h1 = __float2bfloat16(v.y);
    __nv_bfloat16 h2 = __float2bfloat16(v.z), h3 = __float2bfloat16(v.w);
    __nv_bfloat162* hp = (__nv_bfloat162*)(hi + i * 4);
    __nv_bfloat162* lp = (__nv_bfloat162*)(lo + i * 4);
    hp[0] = __nv_bfloat162(h0, h1);
    hp[1] = __nv_bfloat162(h2, h3);
    lp[0] = __nv_bfloat162(__float2bfloat16(v.x - __bfloat162float(h0)),
                           __float2bfloat16(v.y - __bfloat162float(h1)));
    lp[1] = __nv_bfloat162(__float2bfloat16(v.z - __bfloat162float(h2)),
                           __float2bfloat16(v.w - __bfloat162float(h3)));
}

// ---- bf16x3 mma.sync GEMM (unchanged, validated) ----------------------------
#define BM 128
#define BN 128
#define BK 32
#define SROW 40
#define TILE_E (128 * SROW)
#define STAGE_E (4 * TILE_E)
#define SMEM_SZ (2 * STAGE_E * 2)

__global__ __launch_bounds__(256, 1)
void gemm_bf16x3(const __nv_bfloat16* __restrict__ Ahi, const __nv_bfloat16* __restrict__ Alo,
                 const __nv_bfloat16* __restrict__ Bhi, const __nv_bfloat16* __restrict__ Blo,
                 const float* __restrict__ bias, float* __restrict__ C,
                 int M, int N, int K)
{
    extern __shared__ __nv_bfloat16 smem[];
    const int tid  = threadIdx.x;
    const int lane = tid & 31;
    const int wid  = tid >> 5;
    const int wm   = wid >> 2;
    const int wn   = wid & 3;
    const int tr   = lane >> 2;
    const int tc2  = (lane & 3) * 2;
    const int bm   = blockIdx.y * BM;
    const int bn   = blockIdx.x * BN;

    const uint32_t sbase = smem_u32(smem);

    float acc[4][4][4];
#pragma unroll
    for (int i = 0; i < 4; ++i)
#pragma unroll
        for (int j = 0; j < 4; ++j)
#pragma unroll
            for (int r = 0; r < 4; ++r) acc[i][j][r] = 0.f;

    const __nv_bfloat16* srcs[4] = { Ahi, Alo, Bhi, Blo };
    const int rowoff[4] = { bm, bm, bn, bn };

    auto load_stage = [&](int s, int k0) {
        const uint32_t st = sbase + (uint32_t)(s * STAGE_E * 2);
#pragma unroll
        for (int t = 0; t < 4; ++t) {
#pragma unroll
            for (int g2 = 0; g2 < 2; ++g2) {
                const int g = tid + g2 * 256;
                const int row = g >> 2, part = g & 3;
                const uint32_t dst = st + (uint32_t)(t * TILE_E + row * SROW + part * 8) * 2;
                const __nv_bfloat16* src = srcs[t] + (size_t)(rowoff[t] + row) * K + k0 + part * 8;
                cp16(dst, src);
            }
        }
    };

    const int KCH = K / BK;
    load_stage(0, 0);
    CP_COMMIT();

    for (int c = 0; c < KCH; ++c) {
        if (c + 1 < KCH) {
            load_stage((c + 1) & 1, (c + 1) * BK);
            CP_COMMIT();
            CP_WAIT(1);
        } else {
            CP_WAIT(0);
        }
        __syncthreads();

        const __nv_bfloat16* stg = smem + (c & 1) * STAGE_E;
        const __nv_bfloat16* Ah = stg;
        const __nv_bfloat16* Al = stg + TILE_E;
        const __nv_bfloat16* Bh = stg + 2 * TILE_E;
        const __nv_bfloat16* Bl = stg + 3 * TILE_E;

#pragma unroll
        for (int k0 = 0; k0 < BK; k0 += 16) {
            uint32_t ah[4][4], al[4][4], bh[4][2], bl[4][2];
#pragma unroll
            for (int mi = 0; mi < 4; ++mi) {
                const int base = (wm * 64 + mi * 16 + tr) * SROW + k0 + tc2;
                ah[mi][0] = *(const uint32_t*)(Ah + base);
                ah[mi][1] = *(const uint32_t*)(Ah + base + 8 * SROW);
                ah[mi][2] = *(const uint32_t*)(Ah + base + 8);
                ah[mi][3] = *(const uint32_t*)(Ah + base + 8 * SROW + 8);
                al[mi][0] = *(const uint32_t*)(Al + base);
                al[mi][1] = *(const uint32_t*)(Al + base + 8 * SROW);
                al[mi][2] = *(const uint32_t*)(Al + base + 8);
                al[mi][3] = *(const uint32_t*)(Al + base + 8 * SROW + 8);
            }
#pragma unroll
            for (int ni = 0; ni < 4; ++ni) {
                const int base = (wn * 32 + ni * 8 + tr) * SROW + k0 + tc2;
                bh[ni][0] = *(const uint32_t*)(Bh + base);
                bh[ni][1] = *(const uint32_t*)(Bh + base + 8);
                bl[ni][0] = *(const uint32_t*)(Bl + base);
                bl[ni][1] = *(const uint32_t*)(Bl + base + 8);
            }
#pragma unroll
            for (int mi = 0; mi < 4; ++mi)
#pragma unroll
                for (int ni = 0; ni < 4; ++ni) {
                    mma_bf16(acc[mi][ni], ah[mi][0], ah[mi][1], ah[mi][2], ah[mi][3],
                             bh[ni][0], bh[ni][1]);
                    mma_bf16(acc[mi][ni], al[mi][0], al[mi][1], al[mi][2], al[mi][3],
                             bh[ni][0], bh[ni][1]);
                    mma_bf16(acc[mi][ni], ah[mi][0], ah[mi][1], ah[mi][2], ah[mi][3],
                             bl[ni][0], bl[ni][1]);
                }
        }
        __syncthreads();
    }

#pragma unroll
    for (int mi = 0; mi < 4; ++mi) {
        const int r = bm + wm * 64 + mi * 16 + tr;
#pragma unroll
        for (int ni = 0; ni < 4; ++ni) {
            const int cidx = bn + wn * 32 + ni * 8 + tc2;
            const float b0 = bias[cidx], b1 = bias[cidx + 1];
            float2 v0 = make_float2(acc[mi][ni][0] + b0, acc[mi][ni][1] + b1);
            float2 v1 = make_float2(acc[mi][ni][2] + b0, acc[mi][ni][3] + b1);
            *(float2*)(C + (size_t)r * N + cidx)       = v0;
            *(float2*)(C + (size_t)(r + 8) * N + cidx) = v1;
        }
    }
}

// ---- tensor-core sliding-window attention (direct-LDS fragments only) -------
// 128 threads (4 warps), one (b,h) x 64-query tile. Warp w owns rows 16w..16w+15.
// V stored TRANSPOSED in smem (Vt[e][key]) so its B-fragment is the same
// validated direct-load pattern as K.
#define SROW2 72
#define QTILE_E (64 * SROW2)
#define SWA_SMEM (6 * QTILE_E * 2)

__device__ __forceinline__ void store_hilo(__nv_bfloat16* H, __nv_bfloat16* L,
                                           int off, float4 v) {
    __nv_bfloat16 h0 = __float2bfloat16(v.x), h1 = __float2bfloat16(v.y);
    __nv_bfloat16 h2 = __float2bfloat16(v.z), h3 = __float2bfloat16(v.w);
    *(__nv_bfloat162*)(H + off)     = __nv_bfloat162(h0, h1);
    *(__nv_bfloat162*)(H + off + 2) = __nv_bfloat162(h2, h3);
    *(__nv_bfloat162*)(L + off)     = __nv_bfloat162(
        __float2bfloat16(v.x - __bfloat162float(h0)),
        __float2bfloat16(v.y - __bfloat162float(h1)));
    *(__nv_bfloat162*)(L + off + 2) = __nv_bfloat162(
        __float2bfloat16(v.z - __bfloat162float(h2)),
        __float2bfloat16(v.w - __bfloat162float(h3)));
}

__global__ __launch_bounds__(128, 2)
void swa_tensor(const float* __restrict__ qkv,
                __nv_bfloat16* __restrict__ ohi, __nv_bfloat16* __restrict__ olo)
{
    extern __shared__ __nv_bfloat16 sm[];
    __nv_bfloat16* Qh  = sm;
    __nv_bfloat16* Ql  = sm + 1 * QTILE_E;
    __nv_bfloat16* Kh  = sm + 2 * QTILE_E;
    __nv_bfloat16* Kl  = sm + 3 * QTILE_E;
    __nv_bfloat16* Vth = sm + 4 * QTILE_E;   // [e][key]
    __nv_bfloat16* Vtl = sm + 5 * QTILE_E;

    const int tid = threadIdx.x, lane = tid & 31, w = tid >> 5;
    const int bh = blockIdx.y, b = bh >> 4, h = bh & 15;
    const int q0 = blockIdx.x * 64;
    const int tr = lane >> 2, tc2 = (lane & 3) * 2;

    const size_t rowbase = (size_t)(b * SEQ) * QKV_LD + (size_t)h * HDIM;

    // ---- Q tile -> smem hi/lo ----
#pragma unroll
    for (int it = 0; it < 8; ++it) {
        const int idx = it * 128 + tid;
        const int row = idx >> 4, c4 = (idx & 15) * 4;
        float4 v = *(const float4*)(qkv + rowbase + (size_t)(q0 + row) * QKV_LD + c4);
        store_hilo(Qh, Ql, row * SROW2 + c4, v);
    }
    __syncthreads();

    // ---- Q A-fragments via direct LDS (gemm-validated pattern) ----
    uint32_t qh[4][4], ql[4][4];
#pragma unroll
    for (int ks = 0; ks < 4; ++ks) {
        const int base = (w * 16 + tr) * SROW2 + ks * 16 + tc2;
        qh[ks][0] = *(const uint32_t*)(Qh + base);
        qh[ks][1] = *(const uint32_t*)(Qh + base + 8 * SROW2);
        qh[ks][2] = *(const uint32_t*)(Qh + base + 8);
        qh[ks][3] = *(const uint32_t*)(Qh + base + 8 * SROW2 + 8);
        ql[ks][0] = *(const uint32_t*)(Ql + base);
        ql[ks][1] = *(const uint32_t*)(Ql + base + 8 * SROW2);
        ql[ks][2] = *(const uint32_t*)(Ql + base + 8);
        ql[ks][3] = *(const uint32_t*)(Ql + base + 8 * SROW2 + 8);
    }

    float o[8][4];
#pragma unroll
    for (int ni = 0; ni < 8; ++ni)
#pragma unroll
        for (int j = 0; j < 4; ++j) o[ni][j] = 0.f;
    float m0 = -1e30f, m1 = -1e30f, l0 = 0.f, l1 = 0.f;
    const int i0 = q0 + w * 16 + tr;     // global row for d0,d1
    const int i1 = i0 + 8;               // global row for d2,d3

    const int kt0 = max(0, (int)blockIdx.x - 4);
    const int kt1 = blockIdx.x;

    for (int kt = kt0; kt <= kt1; ++kt) {
        const int j0 = kt * 64;
        __syncthreads();
#pragma unroll
        for (int it = 0; it < 8; ++it) {
            const int idx = it * 128 + tid;
            const int row = idx >> 4, c4 = (idx & 15) * 4;   // row = key, c4 = e
            const size_t rb = rowbase + (size_t)(j0 + row) * QKV_LD;
            float4 kv = *(const float4*)(qkv + rb + D_MODEL + c4);
            float4 vv = *(const float4*)(qkv + rb + 2 * D_MODEL + c4);
            store_hilo(Kh, Kl, row * SROW2 + c4, kv);
            // V transposed: Vt[e][key]
            const float vf[4] = { vv.x, vv.y, vv.z, vv.w };
#pragma unroll
            for (int j = 0; j < 4; ++j) {
                __nv_bfloat16 hv = __float2bfloat16(vf[j]);
                Vth[(c4 + j) * SROW2 + row] = hv;
                Vtl[(c4 + j) * SROW2 + row] =
                    __float2bfloat16(vf[j] - __bfloat162float(hv));
            }
        }
        __syncthreads();

        // ---- S = Q K^T (bf16x3), B-fragments via direct LDS ----
        float s[8][4];
#pragma unroll
        for (int ni = 0; ni < 8; ++ni)
#pragma unroll
            for (int j = 0; j < 4; ++j) s[ni][j] = 0.f;

#pragma unroll
        for (int ni = 0; ni < 8; ++ni) {          // key 8-block
#pragma unroll
            for (int ks = 0; ks < 4; ++ks) {      // e 16-block
                const int base = (ni * 8 + tr) * SROW2 + ks * 16 + tc2;
                const uint32_t kb0 = *(const uint32_t*)(Kh + base);
                const uint32_t kb1 = *(const uint32_t*)(Kh + base + 8);
                const uint32_t kl0 = *(const uint32_t*)(Kl + base);
                const uint32_t kl1 = *(const uint32_t*)(Kl + base + 8);
                mma_bf16(s[ni], qh[ks][0], qh[ks][1], qh[ks][2], qh[ks][3], kb0, kb1);
                mma_bf16(s[ni], ql[ks][0], ql[ks][1], ql[ks][2], ql[ks][3], kb0, kb1);
                mma_bf16(s[ni], qh[ks][0], qh[ks][1], qh[ks][2], qh[ks][3], kl0, kl1);
            }
        }

        // ---- mask + online softmax ----
        float tmax0 = -1e30f, tmax1 = -1e30f;
#pragma unroll
        for (int ni = 0; ni < 8; ++ni) {
            const int ja = j0 + ni * 8 + tc2, jb = ja + 1;
            s[ni][0] = (ja <= i0 && (i0 - ja) < WINDOW) ? s[ni][0] * 0.125f : -1e30f;
            s[ni][1] = (jb <= i0 && (i0 - jb) < WINDOW) ? s[ni][1] * 0.125f : -1e30f;
            s[ni][2] = (ja <= i1 && (i1 - ja) < WINDOW) ? s[ni][2] * 0.125f : -1e30f;
            s[ni][3] = (jb <= i1 && (i1 - jb) < WINDOW) ? s[ni][3] * 0.125f : -1e30f;
            tmax0 = fmaxf(tmax0, fmaxf(s[ni][0], s[ni][1]));
            tmax1 = fmaxf(tmax1, fmaxf(s[ni][2], s[ni][3]));
        }
        tmax0 = fmaxf(tmax0, __shfl_xor_sync(0xffffffff, tmax0, 1));
        tmax0 = fmaxf(tmax0, __shfl_xor_sync(0xffffffff, tmax0, 2));
        tmax1 = fmaxf(tmax1, __shfl_xor_sync(0xffffffff, tmax1, 1));
        tmax1 = fmaxf(tmax1, __shfl_xor_sync(0xffffffff, tmax1, 2));

        const float mn0 = fmaxf(m0, tmax0), mn1 = fmaxf(m1, tmax1);
        const float sc0 = __expf(m0 - mn0), sc1 = __expf(m1 - mn1);
        m0 = mn0; m1 = mn1;

        float rs0 = 0.f, rs1 = 0.f;
        uint32_t ph[8][2], pl[8][2];
#pragma unroll
        for (int ni = 0; ni < 8; ++ni) {
            float p0 = __expf(s[ni][0] - mn0);
            float p1 = __expf(s[ni][1] - mn0);
            float p2 = __expf(s[ni][2] - mn1);
            float p3 = __expf(s[ni][3] - mn1);
            rs0 += p0 + p1; rs1 += p2 + p3;
            __nv_bfloat16 b0 = __float2bfloat16(p0), b1 = __float2bfloat16(p1);
            __nv_bfloat16 b2 = __float2bfloat16(p2), b3 = __float2bfloat16(p3);
            __nv_bfloat162 t01(b0, b1), t23(b2, b3);
            ph[ni][0] = *(uint32_t*)&t01;
            ph[ni][1] = *(uint32_t*)&t23;
            pl[ni][0] = pack_bf16(p0 - __bfloat162float(b0), p1 - __bfloat162float(b1));
            pl[ni][1] = pack_bf16(p2 - __bfloat162float(b2), p3 - __bfloat162float(b3));
        }
        rs0 += __shfl_xor_sync(0xffffffff, rs0, 1);
        rs0 += __shfl_xor_sync(0xffffffff, rs0, 2);
        rs1 += __shfl_xor_sync(0xffffffff, rs1, 1);
        rs1 += __shfl_xor_sync(0xffffffff, rs1, 2);
        l0 = l0 * sc0 + rs0;
        l1 = l1 * sc1 + rs1;

#pragma unroll
        for (int ni = 0; ni < 8; ++ni) {
            o[ni][0] *= sc0; o[ni][1] *= sc0;
            o[ni][2] *= sc1; o[ni][3] *= sc1;
        }

        // ---- O += P V (bf16x3); V B-fragments from transposed smem ----
#pragma unroll
        for (int ni = 0; ni < 8; ++ni) {          // e 8-block (output cols)
#pragma unroll
            for (int ks = 0; ks < 4; ++ks) {      // key 16-block
                const int base = (ni * 8 + tr) * SROW2 + ks * 16 + tc2;
                const uint32_t vb0 = *(const uint32_t*)(Vth + base);
                const uint32_t vb1 = *(const uint32_t*)(Vth + base + 8);
                const uint32_t vl0 = *(const uint32_t*)(Vtl + base);
                const uint32_t vl1 = *(const uint32_t*)(Vtl + base + 8);
                mma_bf16(o[ni], ph[2*ks][0], ph[2*ks][1], ph[2*ks+1][0], ph[2*ks+1][1], vb0, vb1);
                mma_bf16(o[ni], pl[2*ks][0], pl[2*ks][1], pl[2*ks+1][0], pl[2*ks+1][1], vb0, vb1);
                mma_bf16(o[ni], ph[2*ks][0], ph[2*ks][1], ph[2*ks+1][0], ph[2*ks+1][1], vl0, vl1);
            }
        }
    }

    // ---- epilogue: O/l -> bf16 hi/lo ----
    const float inv0 = 1.f / l0, inv1 = 1.f / l1;
    const size_t t0 = (size_t)(b * SEQ + i0) * D_MODEL + (size_t)h * HDIM;
    const size_t t1 = (size_t)(b * SEQ + i1) * D_MODEL + (size_t)h * HDIM;
#pragma unroll
    for (int ni = 0; ni < 8; ++ni) {
        const int c = ni * 8 + tc2;
        float f0 = o[ni][0] * inv0, f1 = o[ni][1] * inv0;
        float f2 = o[ni][2] * inv1, f3 = o[ni][3] * inv1;
        __nv_bfloat16 h0 = __float2bfloat16(f0), h1 = __float2bfloat16(f1);
        __nv_bfloat16 h2 = __float2bfloat16(f2), h3 = __float2bfloat16(f3);
        __nv_bfloat162 u01(h0, h1), u23(h2, h3);
        *(uint32_t*)(ohi + t0 + c) = *(uint32_t*)&u01;
        *(uint32_t*)(ohi + t1 + c) = *(uint32_t*)&u23;
        *(uint32_t*)(olo + t0 + c) = pack_bf16(f0 - __bfloat162float(h0),
                                               f1 - __bfloat162float(h1));
        *(uint32_t*)(olo + t1 + c) = pack_bf16(f2 - __bfloat162float(h2),
                                               f3 - __bfloat162float(h3));
    }
}

// ---------------------------------------------------------------------------
extern "C" void kernel_launch(void* const* d_in, const int* in_sizes, int n_in,
                              void* d_out, int out_size)
{
    const float* x      = (const float*)d_in[0];
    const float* w_qkv  = (const float*)d_in[1];
    const float* b_qkv  = (const float*)d_in[2];
    const float* w_proj = (const float*)d_in[3];
    const float* b_proj = (const float*)d_in[4];
    float* out = (float*)d_out;

    float* qkv_p;
    __nv_bfloat16 *xhi, *xlo, *wqh, *wql, *wph, *wpl, *ahi, *alo;
    cudaGetSymbolAddress((void**)&qkv_p, g_qkv);
    cudaGetSymbolAddress((void**)&xhi, g_xhi);
    cudaGetSymbolAddress((void**)&xlo, g_xlo);
    cudaGetSymbolAddress((void**)&wqh, g_wqh);
    cudaGetSymbolAddress((void**)&wql, g_wql);
    cudaGetSymbolAddress((void**)&wph, g_wph);
    cudaGetSymbolAddress((void**)&wpl, g_wpl);
    cudaGetSymbolAddress((void**)&ahi, g_ahi);
    cudaGetSymbolAddress((void**)&alo, g_alo);

    cudaFuncSetAttribute(gemm_bf16x3,
                         cudaFuncAttributeMaxDynamicSharedMemorySize, SMEM_SZ);
    cudaFuncSetAttribute(swa_tensor,
                         cudaFuncAttributeMaxDynamicSharedMemorySize, SWA_SMEM);

    {
        int n4x = MTOT * D_MODEL / 4;
        int n4q = QKV_LD * D_MODEL / 4;
        int n4p = D_MODEL * D_MODEL / 4;
        split_bf16<<<n4x / 256, 256>>>((const float4*)x, xhi, xlo, n4x);
        split_bf16<<<n4q / 256, 256>>>((const float4*)w_qkv, wqh, wql, n4q);
        split_bf16<<<n4p / 256, 256>>>((const float4*)w_proj, wph, wpl, n4p);
    }

    // 1) QKV projection (bf16x3 tensor-core)
    gemm_bf16x3<<<dim3(QKV_LD / BN, MTOT / BM), 256, SMEM_SZ>>>(
        xhi, xlo, wqh, wql, b_qkv, qkv_p, MTOT, QKV_LD, D_MODEL);

    // 2) tensor-core sliding-window attention -> bf16 hi/lo
    swa_tensor<<<dim3(SEQ / 64, BATCH * NHEADS), 128, SWA_SMEM>>>(qkv_p, ahi, alo);

    // 3) output projection (bf16x3 tensor-core)
    gemm_bf16x3<<<dim3(D_MODEL / BN, MTOT / BM), 256, SMEM_SZ>>>(
        ahi, alo, wph, wpl, b_proj, out, MTOT, D_MODEL, D_MODEL);
}